// round 10
// baseline (speedup 1.0000x reference)
#include <cuda_runtime.h>
#include <math.h>
#include <float.h>

#define NPIL 60000
#define PPTS 32
#define SBLK 469   // k_stats: 128 threads/block, one pillar per thread

// moment partials, entry-major for coalesced reduction:
// entry t: [0..3]=M1(sum u), [4..13]=M2 tri4, [14..37]=X[i*6+j]=sum(S_i*alpha_j),
//          [38..58]=A2 tri6 (nv*alpha_a*alpha_b), [59..64]=A1 (nv*alpha_j)
static __device__ float g_part[65][SBLK];
// per-channel folded params, 16 floats each (4 float4s)
static __device__ float g_params[64 * 16];
// per-pillar mean + center: [2i]={mx,my,mz,-}, [2i+1]={cx,cy,cz,-}
static __device__ float4 g_pm[NPIL * 2];

__device__ __forceinline__ float wredsum(float v) {
#pragma unroll
    for (int s = 16; s > 0; s >>= 1) v += __shfl_xor_sync(0xffffffffu, v, s);
    return v;
}

// ---------------------------------------------------------------------------
// k_stats: THREAD per pillar — zero shuffles in the hot loop.
// Each thread streams its pillar's 32 points (masked loop runs nv iters),
// then the warp reduces all 65 moment entries once (entries computed on the
// fly from S, alpha, M2, nv — never 65 live registers).
// ---------------------------------------------------------------------------
__global__ void __launch_bounds__(128) k_stats(const float4* __restrict__ pts,
                                               const int* __restrict__ nvs,
                                               const int4* __restrict__ coords) {
    __shared__ float sE[4][65];
    const int lane = threadIdx.x & 31;
    const int warp = threadIdx.x >> 5;
    const int i = blockIdx.x * 128 + threadIdx.x;
    const bool ok = (i < NPIL);

    float S[4]  = {0.0f, 0.0f, 0.0f, 0.0f};
    float M2[10];
#pragma unroll
    for (int k = 0; k < 10; k++) M2[k] = 0.0f;
    float al[6] = {0.0f, 0.0f, 0.0f, 0.0f, 0.0f, 0.0f};
    float nvf = 0.0f;

    if (ok) {
        const int nv = nvs[i];
        const int4 c = coords[i];
        const float4* __restrict__ base = pts + i * PPTS;
        float ix = 0.0f, iy = 0.0f, iz = 0.0f;   // invalid-lane xyz sum

        for (int p = 0; p < nv; p++) {           // valid points
            const float4 q = base[p];
            S[0] += q.x; S[1] += q.y; S[2] += q.z; S[3] += q.w;
            M2[0] = fmaf(q.x, q.x, M2[0]); M2[1] = fmaf(q.x, q.y, M2[1]);
            M2[2] = fmaf(q.x, q.z, M2[2]); M2[3] = fmaf(q.x, q.w, M2[3]);
            M2[4] = fmaf(q.y, q.y, M2[4]); M2[5] = fmaf(q.y, q.z, M2[5]);
            M2[6] = fmaf(q.y, q.w, M2[6]); M2[7] = fmaf(q.z, q.z, M2[7]);
            M2[8] = fmaf(q.z, q.w, M2[8]); M2[9] = fmaf(q.w, q.w, M2[9]);
        }
        for (int p = nv; p < PPTS; p++) {        // masked points: only unmasked mean
            const float4 q = base[p];
            ix += q.x; iy += q.y; iz += q.z;
        }

        nvf = (float)nv;
        const float inv = 1.0f / nvf;
        al[0] = (S[0] + ix) * inv;               // mean over ALL 32, / nv (ref semantics)
        al[1] = (S[1] + iy) * inv;
        al[2] = (S[2] + iz) * inv;
        al[3] = (float)c.w * 0.2f + 0.1f;
        al[4] = (float)c.z * 0.2f - 39.9f;
        al[5] = (float)c.y * 4.0f - 1.0f;

        g_pm[2 * i]     = make_float4(al[0], al[1], al[2], 0.0f);
        g_pm[2 * i + 1] = make_float4(al[3], al[4], al[5], 0.0f);
    }

    // warp-reduce all 65 entries (invalid lanes contribute zeros)
#pragma unroll
    for (int k = 0; k < 4; k++) {
        const float v = wredsum(S[k]);
        if (lane == 0) sE[warp][k] = v;
    }
#pragma unroll
    for (int k = 0; k < 10; k++) {
        const float v = wredsum(M2[k]);
        if (lane == 0) sE[warp][4 + k] = v;
    }
#pragma unroll
    for (int a = 0; a < 4; a++)
#pragma unroll
        for (int j = 0; j < 6; j++) {
            const float v = wredsum(S[a] * al[j]);
            if (lane == 0) sE[warp][14 + a * 6 + j] = v;
        }
#pragma unroll
    for (int a = 0; a < 6; a++)
#pragma unroll
        for (int b = 0; b < 6; b++) {
            if (b < a) continue;
            const float v = wredsum(nvf * al[a] * al[b]);
            if (lane == 0) sE[warp][38 + (a * 6 - a * (a - 1) / 2 + (b - a))] = v;
        }
#pragma unroll
    for (int j = 0; j < 6; j++) {
        const float v = wredsum(nvf * al[j]);
        if (lane == 0) sE[warp][59 + j] = v;
    }
    __syncthreads();

    const int t = threadIdx.x;
    if (t < 65) {
        g_part[t][blockIdx.x] = (sE[0][t] + sE[1][t]) + (sE[2][t] + sE[3][t]);
    }
}

// ---------------------------------------------------------------------------
// k_bn: parallel reduce of g_part (8 threads per entry), then per-channel
// BN-folded param derivation in double precision.
// ---------------------------------------------------------------------------
__global__ void __launch_bounds__(544) k_bn(const float* __restrict__ W,
                                            const float* __restrict__ gamma,
                                            const float* __restrict__ beta) {
    __shared__ float sp8[65][8];
    __shared__ float s_acc[65];
    const int t = threadIdx.x;
    if (t < 520) {
        const int e = t >> 3;
        const int s = t & 7;
        const float* row = g_part[e];
        float acc = 0.0f;
        for (int k = 0; k < 59; k++) {            // 469 <= 8*59
            const int idx = s + 8 * k;
            if (idx < SBLK) acc += row[idx];
        }
        sp8[e][s] = acc;
    }
    __syncthreads();
    if (t < 65) {
        const float* r = sp8[t];
        s_acc[t] = ((r[0] + r[1]) + (r[2] + r[3])) + ((r[4] + r[5]) + (r[6] + r[7]));
    }
    __syncthreads();
    if (t >= 64) return;
    const int o = t;

    const int pidx[10] = {0, 1, 2, 3, 0, 1, 2, 0, 1, 2};
    const int aidx[10] = {-1, -1, -1, -1, 0, 1, 2, 3, 4, 5};

    double w[10];
#pragma unroll
    for (int cc = 0; cc < 10; cc++) w[cc] = (double)W[o * 10 + cc];
    const double NP = (double)NPIL * (double)PPTS;

    double mean = 0.0;
#pragma unroll
    for (int a = 0; a < 10; a++) {
        double g1 = (double)s_acc[pidx[a]];
        if (aidx[a] >= 0) g1 -= (double)s_acc[59 + aidx[a]];
        mean += w[a] * g1;
    }
    mean /= NP;

    double e2 = 0.0;
#pragma unroll
    for (int a = 0; a < 10; a++) {
#pragma unroll
        for (int b = 0; b < 10; b++) {
            if (b < a) continue;
            const int pa = pidx[a], pb = pidx[b];
            const int i4 = (pa <= pb) ? pa : pb;
            const int j4 = (pa <= pb) ? pb : pa;
            double g2 = (double)s_acc[4 + (i4 * 4 - i4 * (i4 - 1) / 2 + (j4 - i4))];
            if (aidx[a] >= 0) g2 -= (double)s_acc[14 + pb * 6 + aidx[a]];
            if (aidx[b] >= 0) g2 -= (double)s_acc[14 + pa * 6 + aidx[b]];
            if (aidx[a] >= 0 && aidx[b] >= 0) {
                const int i6 = (aidx[a] <= aidx[b]) ? aidx[a] : aidx[b];
                const int j6 = (aidx[a] <= aidx[b]) ? aidx[b] : aidx[a];
                g2 += (double)s_acc[38 + (i6 * 6 - i6 * (i6 - 1) / 2 + (j6 - i6))];
            }
            e2 += w[a] * w[b] * g2 * ((a == b) ? 1.0 : 2.0);
        }
    }
    e2 /= NP;

    const double var = e2 - mean * mean;
    const double aa = (double)gamma[o] / sqrt(var + 1e-3);
    const double bb = (double)beta[o] - mean * aa;
    float* p = g_params + o * 16;
    p[0]  = (float)(aa * (w[0] + w[4] + w[7]));
    p[1]  = (float)(aa * (w[1] + w[5] + w[8]));
    p[2]  = (float)(aa * (w[2] + w[6] + w[9]));
    p[3]  = (float)(aa * w[3]);
    p[4]  = (float)(aa * w[4]);
    p[5]  = (float)(aa * w[5]);
    p[6]  = (float)(aa * w[6]);
    p[7]  = (float)(aa * w[7]);
    p[8]  = (float)(aa * w[8]);
    p[9]  = (float)(aa * w[9]);
    p[10] = (float)bb;
    p[11] = 0.0f;
    p[12] = 0.0f; p[13] = 0.0f; p[14] = 0.0f; p[15] = 0.0f;
}

// ---------------------------------------------------------------------------
// k_out: warp = pillar. Inner nv-bounded max loop over shared tile;
// pb (pillar bias) computed AFTER the loop so pm/pc load latency is hidden;
// next pillar's q/nv prefetched. max_p(pb + d_p) == pb + max_p(d_p).
// ---------------------------------------------------------------------------
__global__ void __launch_bounds__(256) k_out(const float4* __restrict__ pts,
                                             const int* __restrict__ nvs,
                                             float* __restrict__ out) {
    __shared__ float4 sp[8][32];
    const int lane = threadIdx.x & 31;
    const int warp = threadIdx.x >> 5;
    const int gw = blockIdx.x * 8 + warp;
    const int nw = gridDim.x * 8;

    const float4* pp = (const float4*)g_params;
    const float4 wc0 = pp[lane * 4 + 0];
    const float4 m0v = pp[lane * 4 + 1];          // {aW4,aW5,aW6,aW7}
    const float4 t0v = pp[lane * 4 + 2];          // {aW8,aW9,b,pad}
    const float4 wc1 = pp[(lane + 32) * 4 + 0];
    const float4 m1v = pp[(lane + 32) * 4 + 1];
    const float4 t1v = pp[(lane + 32) * 4 + 2];

    int i = gw;
    if (i >= NPIL) return;
    float4 q = pts[i * PPTS + lane];
    int nv = nvs[i];

    for (;;) {
        sp[warp][lane] = q;
        const float4 pm = g_pm[2 * i];        // consumed after the loop
        const float4 pc = g_pm[2 * i + 1];
        __syncwarp();

        const int inext = i + nw;
        const bool more = inext < NPIL;
        float4 qn; int nvn = 0;
        if (more) {                            // prefetch next pillar
            qn = pts[inext * PPTS + lane];
            nvn = nvs[inext];
        }

        const float4* s4 = sp[warp];
        float a0 = -FLT_MAX, b0 = -FLT_MAX, a1 = -FLT_MAX, b1 = -FLT_MAX;
        int p = 0;
        for (; p + 2 <= nv; p += 2) {
            const float4 r0 = s4[p];
            const float4 r1 = s4[p + 1];
            a0 = fmaxf(a0, fmaf(r0.x, wc0.x, fmaf(r0.y, wc0.y, fmaf(r0.z, wc0.z, r0.w * wc0.w))));
            b0 = fmaxf(b0, fmaf(r1.x, wc0.x, fmaf(r1.y, wc0.y, fmaf(r1.z, wc0.z, r1.w * wc0.w))));
            a1 = fmaxf(a1, fmaf(r0.x, wc1.x, fmaf(r0.y, wc1.y, fmaf(r0.z, wc1.z, r0.w * wc1.w))));
            b1 = fmaxf(b1, fmaf(r1.x, wc1.x, fmaf(r1.y, wc1.y, fmaf(r1.z, wc1.z, r1.w * wc1.w))));
        }
        if (p < nv) {
            const float4 r0 = s4[p];
            a0 = fmaxf(a0, fmaf(r0.x, wc0.x, fmaf(r0.y, wc0.y, fmaf(r0.z, wc0.z, r0.w * wc0.w))));
            a1 = fmaxf(a1, fmaf(r0.x, wc1.x, fmaf(r0.y, wc1.y, fmaf(r0.z, wc1.z, r0.w * wc1.w))));
        }
        __syncwarp();

        const float pb0 = t0v.z - (pm.x * m0v.x + pm.y * m0v.y + pm.z * m0v.z)
                                - (pc.x * m0v.w + pc.y * t0v.x + pc.z * t0v.y);
        const float pb1 = t1v.z - (pm.x * m1v.x + pm.y * m1v.y + pm.z * m1v.z)
                                - (pc.x * m1v.w + pc.y * t1v.x + pc.z * t1v.y);

        float r0 = pb0 + fmaxf(a0, b0);
        float r1 = pb1 + fmaxf(a1, b1);
        if (nv < PPTS) {   // masked points contribute exactly b pre-ReLU
            r0 = fmaxf(r0, t0v.z);
            r1 = fmaxf(r1, t1v.z);
        }
        out[i * 64 + lane]      = fmaxf(r0, 0.0f);
        out[i * 64 + 32 + lane] = fmaxf(r1, 0.0f);

        if (!more) break;
        i = inext; q = qn; nv = nvn;
    }
}

extern "C" void kernel_launch(void* const* d_in, const int* in_sizes, int n_in,
                              void* d_out, int out_size) {
    const float4* feats  = (const float4*)d_in[0];
    const int*    nvs    = (const int*)d_in[1];
    const int4*   coords = (const int4*)d_in[2];
    const float*  W      = (const float*)d_in[3];
    const float*  gamma  = (const float*)d_in[4];
    const float*  beta   = (const float*)d_in[5];
    float* out = (float*)d_out;

    k_stats<<<SBLK, 128>>>(feats, nvs, coords);
    k_bn<<<1, 544>>>(W, gamma, beta);
    k_out<<<1184, 256>>>(feats, nvs, out);
}

// round 12
// speedup vs baseline: 1.0358x; 1.0358x over previous
#include <cuda_runtime.h>
#include <math.h>
#include <float.h>

#define NPIL 60000
#define PPTS 32
#define SBLK 938   // k_stats: 128 thr/block, TWO threads per pillar (120064 threads)

// moment partials, entry-major for coalesced reduction:
// entry t: [0..3]=M1(sum u), [4..13]=M2 tri4, [14..37]=X[i*6+j]=sum(S_i*alpha_j),
//          [38..58]=A2 tri6 (nv*alpha_a*alpha_b), [59..64]=A1 (nv*alpha_j)
static __device__ float g_part[65][SBLK];
// per-channel folded params, 16 floats each (4 float4s)
static __device__ float g_params[64 * 16];
// per-pillar mean + center: [2i]={mx,my,mz,-}, [2i+1]={cx,cy,cz,-}
static __device__ float4 g_pm[NPIL * 2];

__device__ __forceinline__ float wredsum(float v) {
#pragma unroll
    for (int s = 16; s > 0; s >>= 1) v += __shfl_xor_sync(0xffffffffu, v, s);
    return v;
}

// ---------------------------------------------------------------------------
// k_stats: TWO threads per pillar (16 points each) — halves the per-thread
// serial chain and doubles resident warps vs thread-per-pillar. Partner pair
// merges S / unmasked-xyz via one shfl_xor(1); the even thread owns the
// pillar-level alpha products; M2 partials stay per-thread (sum is exact).
// ---------------------------------------------------------------------------
__global__ void __launch_bounds__(128) k_stats(const float4* __restrict__ pts,
                                               const int* __restrict__ nvs,
                                               const int4* __restrict__ coords) {
    __shared__ float sE[4][65];
    const int lane = threadIdx.x & 31;
    const int warp = threadIdx.x >> 5;
    const int j = blockIdx.x * 128 + threadIdx.x;
    const int i = j >> 1;
    const int half = j & 1;
    const bool ok = (i < NPIL);

    float S[4]  = {0.0f, 0.0f, 0.0f, 0.0f};
    float M2[10];
#pragma unroll
    for (int k = 0; k < 10; k++) M2[k] = 0.0f;
    float al[6] = {0.0f, 0.0f, 0.0f, 0.0f, 0.0f, 0.0f};
    float nvf = 0.0f;
    float ix = 0.0f, iy = 0.0f, iz = 0.0f;
    int nv = 0;
    int4 c = make_int4(0, 0, 0, 0);

    if (ok) {
        nv = nvs[i];
        c = coords[i];
        const float4* __restrict__ base = pts + i * PPTS;
        const int s0 = half * 16;
        const int e_mask = (nv < s0 + 16) ? nv : (s0 + 16);

        for (int p = s0; p < e_mask; p++) {      // valid points in this half
            const float4 q = base[p];
            S[0] += q.x; S[1] += q.y; S[2] += q.z; S[3] += q.w;
            M2[0] = fmaf(q.x, q.x, M2[0]); M2[1] = fmaf(q.x, q.y, M2[1]);
            M2[2] = fmaf(q.x, q.z, M2[2]); M2[3] = fmaf(q.x, q.w, M2[3]);
            M2[4] = fmaf(q.y, q.y, M2[4]); M2[5] = fmaf(q.y, q.z, M2[5]);
            M2[6] = fmaf(q.y, q.w, M2[6]); M2[7] = fmaf(q.z, q.z, M2[7]);
            M2[8] = fmaf(q.z, q.w, M2[8]); M2[9] = fmaf(q.w, q.w, M2[9]);
        }
        const int s1 = (nv > s0) ? nv : s0;
        for (int p = s1; p < s0 + 16; p++) {     // masked points: unmasked-mean only
            const float4 q = base[p];
            ix += q.x; iy += q.y; iz += q.z;
        }
    }

    // merge partner halves (pairs are adjacent lanes)
    const float Sx = S[0] + __shfl_xor_sync(0xffffffffu, S[0], 1);
    const float Sy = S[1] + __shfl_xor_sync(0xffffffffu, S[1], 1);
    const float Sz = S[2] + __shfl_xor_sync(0xffffffffu, S[2], 1);
    const float Sw = S[3] + __shfl_xor_sync(0xffffffffu, S[3], 1);
    const float tx = ix + __shfl_xor_sync(0xffffffffu, ix, 1);
    const float ty = iy + __shfl_xor_sync(0xffffffffu, iy, 1);
    const float tz = iz + __shfl_xor_sync(0xffffffffu, iz, 1);

    if (ok && half == 0) {
        S[0] = Sx; S[1] = Sy; S[2] = Sz; S[3] = Sw;
        nvf = (float)nv;
        const float inv = 1.0f / nvf;
        al[0] = (Sx + tx) * inv;                 // mean over ALL 32 points, / nv
        al[1] = (Sy + ty) * inv;
        al[2] = (Sz + tz) * inv;
        al[3] = (float)c.w * 0.2f + 0.1f;
        al[4] = (float)c.z * 0.2f - 39.9f;
        al[5] = (float)c.y * 4.0f - 1.0f;
        g_pm[2 * i]     = make_float4(al[0], al[1], al[2], 0.0f);
        g_pm[2 * i + 1] = make_float4(al[3], al[4], al[5], 0.0f);
    } else {
        S[0] = 0.0f; S[1] = 0.0f; S[2] = 0.0f; S[3] = 0.0f;  // avoid double count
    }

    // warp-reduce all 65 entries (odd / invalid threads contribute zeros
    // except M2, which is a true per-thread partial)
#pragma unroll
    for (int k = 0; k < 4; k++) {
        const float v = wredsum(S[k]);
        if (lane == 0) sE[warp][k] = v;
    }
#pragma unroll
    for (int k = 0; k < 10; k++) {
        const float v = wredsum(M2[k]);
        if (lane == 0) sE[warp][4 + k] = v;
    }
#pragma unroll
    for (int a = 0; a < 4; a++)
#pragma unroll
        for (int jj = 0; jj < 6; jj++) {
            const float v = wredsum(S[a] * al[jj]);
            if (lane == 0) sE[warp][14 + a * 6 + jj] = v;
        }
#pragma unroll
    for (int a = 0; a < 6; a++)
#pragma unroll
        for (int b = 0; b < 6; b++) {
            if (b < a) continue;
            const float v = wredsum(nvf * al[a] * al[b]);
            if (lane == 0) sE[warp][38 + (a * 6 - a * (a - 1) / 2 + (b - a))] = v;
        }
#pragma unroll
    for (int jj = 0; jj < 6; jj++) {
        const float v = wredsum(nvf * al[jj]);
        if (lane == 0) sE[warp][59 + jj] = v;
    }
    __syncthreads();

    const int t = threadIdx.x;
    if (t < 65) {
        g_part[t][blockIdx.x] = (sE[0][t] + sE[1][t]) + (sE[2][t] + sE[3][t]);
    }
}

// ---------------------------------------------------------------------------
// k_bn: parallel reduce of g_part (8 threads per entry), then per-channel
// BN-folded param derivation in double precision.
// ---------------------------------------------------------------------------
__global__ void __launch_bounds__(544) k_bn(const float* __restrict__ W,
                                            const float* __restrict__ gamma,
                                            const float* __restrict__ beta) {
    __shared__ float sp8[65][8];
    __shared__ float s_acc[65];
    const int t = threadIdx.x;
    if (t < 520) {
        const int e = t >> 3;
        const int s = t & 7;
        const float* row = g_part[e];
        float acc = 0.0f;
        for (int k = 0; k < 118; k++) {           // 938 <= 8*118
            const int idx = s + 8 * k;
            if (idx < SBLK) acc += row[idx];
        }
        sp8[e][s] = acc;
    }
    __syncthreads();
    if (t < 65) {
        const float* r = sp8[t];
        s_acc[t] = ((r[0] + r[1]) + (r[2] + r[3])) + ((r[4] + r[5]) + (r[6] + r[7]));
    }
    __syncthreads();
    if (t >= 64) return;
    const int o = t;

    const int pidx[10] = {0, 1, 2, 3, 0, 1, 2, 0, 1, 2};
    const int aidx[10] = {-1, -1, -1, -1, 0, 1, 2, 3, 4, 5};

    double w[10];
#pragma unroll
    for (int cc = 0; cc < 10; cc++) w[cc] = (double)W[o * 10 + cc];
    const double NP = (double)NPIL * (double)PPTS;

    double mean = 0.0;
#pragma unroll
    for (int a = 0; a < 10; a++) {
        double g1 = (double)s_acc[pidx[a]];
        if (aidx[a] >= 0) g1 -= (double)s_acc[59 + aidx[a]];
        mean += w[a] * g1;
    }
    mean /= NP;

    double e2 = 0.0;
#pragma unroll
    for (int a = 0; a < 10; a++) {
#pragma unroll
        for (int b = 0; b < 10; b++) {
            if (b < a) continue;
            const int pa = pidx[a], pb = pidx[b];
            const int i4 = (pa <= pb) ? pa : pb;
            const int j4 = (pa <= pb) ? pb : pa;
            double g2 = (double)s_acc[4 + (i4 * 4 - i4 * (i4 - 1) / 2 + (j4 - i4))];
            if (aidx[a] >= 0) g2 -= (double)s_acc[14 + pb * 6 + aidx[a]];
            if (aidx[b] >= 0) g2 -= (double)s_acc[14 + pa * 6 + aidx[b]];
            if (aidx[a] >= 0 && aidx[b] >= 0) {
                const int i6 = (aidx[a] <= aidx[b]) ? aidx[a] : aidx[b];
                const int j6 = (aidx[a] <= aidx[b]) ? aidx[b] : aidx[a];
                g2 += (double)s_acc[38 + (i6 * 6 - i6 * (i6 - 1) / 2 + (j6 - i6))];
            }
            e2 += w[a] * w[b] * g2 * ((a == b) ? 1.0 : 2.0);
        }
    }
    e2 /= NP;

    const double var = e2 - mean * mean;
    const double aa = (double)gamma[o] / sqrt(var + 1e-3);
    const double bb = (double)beta[o] - mean * aa;
    float* p = g_params + o * 16;
    p[0]  = (float)(aa * (w[0] + w[4] + w[7]));
    p[1]  = (float)(aa * (w[1] + w[5] + w[8]));
    p[2]  = (float)(aa * (w[2] + w[6] + w[9]));
    p[3]  = (float)(aa * w[3]);
    p[4]  = (float)(aa * w[4]);
    p[5]  = (float)(aa * w[5]);
    p[6]  = (float)(aa * w[6]);
    p[7]  = (float)(aa * w[7]);
    p[8]  = (float)(aa * w[8]);
    p[9]  = (float)(aa * w[9]);
    p[10] = (float)bb;
    p[11] = 0.0f;
    p[12] = 0.0f; p[13] = 0.0f; p[14] = 0.0f; p[15] = 0.0f;
}

// ---------------------------------------------------------------------------
// k_out: warp = pillar, SINGLE resident wave (592 blocks = 4/SM).
// Only wc0/wc1 live across the hot loop; the pb coefficient vectors are
// reloaded post-loop via __ldg (L1/L2-hot) to keep registers low.
// max_p(pb + d_p) == pb + max_p(d_p).
// ---------------------------------------------------------------------------
__global__ void __launch_bounds__(256) k_out(const float4* __restrict__ pts,
                                             const int* __restrict__ nvs,
                                             float* __restrict__ out) {
    __shared__ float4 sp[8][32];
    const int lane = threadIdx.x & 31;
    const int warp = threadIdx.x >> 5;
    const int gw = blockIdx.x * 8 + warp;
    const int nw = gridDim.x * 8;

    const float4* pp = (const float4*)g_params;
    const float4 wc0 = pp[lane * 4 + 0];
    const float4 wc1 = pp[(lane + 32) * 4 + 0];

    int i = gw;
    if (i >= NPIL) return;
    float4 q = pts[i * PPTS + lane];
    int nv = nvs[i];

    for (;;) {
        sp[warp][lane] = q;
        const float4 pm = g_pm[2 * i];        // consumed after the loop
        const float4 pc = g_pm[2 * i + 1];
        __syncwarp();

        const int inext = i + nw;
        const bool more = inext < NPIL;
        float4 qn; int nvn = 0;
        if (more) {                            // prefetch next pillar
            qn = pts[inext * PPTS + lane];
            nvn = nvs[inext];
        }

        const float4* s4 = sp[warp];
        float a0 = -FLT_MAX, b0 = -FLT_MAX, a1 = -FLT_MAX, b1 = -FLT_MAX;
        int p = 0;
        for (; p + 2 <= nv; p += 2) {
            const float4 r0 = s4[p];
            const float4 r1 = s4[p + 1];
            a0 = fmaxf(a0, fmaf(r0.x, wc0.x, fmaf(r0.y, wc0.y, fmaf(r0.z, wc0.z, r0.w * wc0.w))));
            b0 = fmaxf(b0, fmaf(r1.x, wc0.x, fmaf(r1.y, wc0.y, fmaf(r1.z, wc0.z, r1.w * wc0.w))));
            a1 = fmaxf(a1, fmaf(r0.x, wc1.x, fmaf(r0.y, wc1.y, fmaf(r0.z, wc1.z, r0.w * wc1.w))));
            b1 = fmaxf(b1, fmaf(r1.x, wc1.x, fmaf(r1.y, wc1.y, fmaf(r1.z, wc1.z, r1.w * wc1.w))));
        }
        if (p < nv) {
            const float4 r0 = s4[p];
            a0 = fmaxf(a0, fmaf(r0.x, wc0.x, fmaf(r0.y, wc0.y, fmaf(r0.z, wc0.z, r0.w * wc0.w))));
            a1 = fmaxf(a1, fmaf(r0.x, wc1.x, fmaf(r0.y, wc1.y, fmaf(r0.z, wc1.z, r0.w * wc1.w))));
        }
        __syncwarp();

        // pb coefficient vectors: reloaded here (not live through the loop)
        const float4 m0v = __ldg(&pp[lane * 4 + 1]);
        const float4 t0v = __ldg(&pp[lane * 4 + 2]);
        const float4 m1v = __ldg(&pp[(lane + 32) * 4 + 1]);
        const float4 t1v = __ldg(&pp[(lane + 32) * 4 + 2]);
        const float pb0 = t0v.z - (pm.x * m0v.x + pm.y * m0v.y + pm.z * m0v.z)
                                - (pc.x * m0v.w + pc.y * t0v.x + pc.z * t0v.y);
        const float pb1 = t1v.z - (pm.x * m1v.x + pm.y * m1v.y + pm.z * m1v.z)
                                - (pc.x * m1v.w + pc.y * t1v.x + pc.z * t1v.y);

        float r0 = pb0 + fmaxf(a0, b0);
        float r1 = pb1 + fmaxf(a1, b1);
        if (nv < PPTS) {   // masked points contribute exactly b pre-ReLU
            r0 = fmaxf(r0, t0v.z);
            r1 = fmaxf(r1, t1v.z);
        }
        out[i * 64 + lane]      = fmaxf(r0, 0.0f);
        out[i * 64 + 32 + lane] = fmaxf(r1, 0.0f);

        if (!more) break;
        i = inext; q = qn; nv = nvn;
    }
}

extern "C" void kernel_launch(void* const* d_in, const int* in_sizes, int n_in,
                              void* d_out, int out_size) {
    const float4* feats  = (const float4*)d_in[0];
    const int*    nvs    = (const int*)d_in[1];
    const int4*   coords = (const int4*)d_in[2];
    const float*  W      = (const float*)d_in[3];
    const float*  gamma  = (const float*)d_in[4];
    const float*  beta   = (const float*)d_in[5];
    float* out = (float*)d_out;

    k_stats<<<SBLK, 128>>>(feats, nvs, coords);
    k_bn<<<1, 544>>>(W, gamma, beta);
    k_out<<<592, 256>>>(feats, nvs, out);
}

// round 13
// speedup vs baseline: 1.0370x; 1.0012x over previous
#include <cuda_runtime.h>
#include <math.h>
#include <float.h>

#define NPIL 60000
#define PPTS 32
#define SBLK 469   // k_stats: 128 thr/block, thread-per-pillar, smem-staged loads

// moment partials, entry-major for coalesced reduction:
// entry t: [0..3]=M1(sum u), [4..13]=M2 tri4, [14..37]=X[i*6+j]=sum(S_i*alpha_j),
//          [38..58]=A2 tri6 (nv*alpha_a*alpha_b), [59..64]=A1 (nv*alpha_j)
static __device__ float g_part[65][SBLK];
// per-channel folded params, 16 floats each (4 float4s)
static __device__ float g_params[64 * 16];
// per-pillar mean + center: [2i]={mx,my,mz,-}, [2i+1]={cx,cy,cz,-}
static __device__ float4 g_pm[NPIL * 2];

__device__ __forceinline__ float wredsum(float v) {
#pragma unroll
    for (int s = 16; s > 0; s >>= 1) v += __shfl_xor_sync(0xffffffffu, v, s);
    return v;
}

// ---------------------------------------------------------------------------
// k_stats: thread-per-pillar compute, COALESCED loads via smem staging.
// Each warp owns 32 consecutive pillars. 4 chunks of 8 points:
//   stage: 8 warp-LDGs, each reading 4 pillars x 8 points (4 contiguous
//          128B lines -> 4 wavefronts, vs 32 for naive thread-major loads)
//   tile[pillar][point] with row stride 9 (odd) -> conflict-free STS/LDS
//   process: lane streams its own pillar's 8 points from smem.
// Epilogue: all 65 moment entries computed on the fly and warp-reduced once.
// ---------------------------------------------------------------------------
__global__ void __launch_bounds__(128) k_stats(const float4* __restrict__ pts,
                                               const int* __restrict__ nvs,
                                               const int4* __restrict__ coords) {
    __shared__ float4 tile[4][32][9];   // [warp][pillar][point(8)+pad]
    __shared__ float sE[4][65];
    const int lane = threadIdx.x & 31;
    const int warp = threadIdx.x >> 5;
    const int warp_base = blockIdx.x * 128 + warp * 32;
    const bool wok = (warp_base < NPIL);      // whole-warp uniform (60000 = 468*128+96)
    const int i = warp_base + lane;           // this thread's pillar

    float S[4]  = {0.0f, 0.0f, 0.0f, 0.0f};
    float M2[10];
#pragma unroll
    for (int k = 0; k < 10; k++) M2[k] = 0.0f;
    float al[6] = {0.0f, 0.0f, 0.0f, 0.0f, 0.0f, 0.0f};
    float nvf = 0.0f;
    float tx = 0.0f, ty = 0.0f, tz = 0.0f;    // unmasked xyz totals

    if (wok) {
        const int nv = nvs[i];
        const int4 c = coords[i];
        const int gsub = lane >> 3;           // 0..3: pillar-within-group
        const int psub = lane & 7;            // 0..7: point-within-chunk

#pragma unroll
        for (int ch = 0; ch < 4; ch++) {
            // stage 32 pillars x 8 points, coalesced
#pragma unroll
            for (int g = 0; g < 8; g++) {
                const int pl = g * 4 + gsub;
                tile[warp][pl][psub] = pts[(warp_base + pl) * PPTS + ch * 8 + psub];
            }
            __syncwarp();
            // process own pillar's 8 points from smem
#pragma unroll
            for (int p = 0; p < 8; p++) {
                const float4 q = tile[warp][lane][p];
                const int pg = ch * 8 + p;
                const float m = (pg < nv) ? 1.0f : 0.0f;
                tx += q.x; ty += q.y; tz += q.z;
                const float ux = q.x * m, uy = q.y * m, uz = q.z * m, uw = q.w * m;
                S[0] += ux; S[1] += uy; S[2] += uz; S[3] += uw;
                M2[0] = fmaf(ux, ux, M2[0]); M2[1] = fmaf(ux, uy, M2[1]);
                M2[2] = fmaf(ux, uz, M2[2]); M2[3] = fmaf(ux, uw, M2[3]);
                M2[4] = fmaf(uy, uy, M2[4]); M2[5] = fmaf(uy, uz, M2[5]);
                M2[6] = fmaf(uy, uw, M2[6]); M2[7] = fmaf(uz, uz, M2[7]);
                M2[8] = fmaf(uz, uw, M2[8]); M2[9] = fmaf(uw, uw, M2[9]);
            }
            __syncwarp();
        }

        nvf = (float)nv;
        const float inv = 1.0f / nvf;
        al[0] = tx * inv;                     // mean over ALL 32 points, / nv (ref)
        al[1] = ty * inv;
        al[2] = tz * inv;
        al[3] = (float)c.w * 0.2f + 0.1f;
        al[4] = (float)c.z * 0.2f - 39.9f;
        al[5] = (float)c.y * 4.0f - 1.0f;
        g_pm[2 * i]     = make_float4(al[0], al[1], al[2], 0.0f);
        g_pm[2 * i + 1] = make_float4(al[3], al[4], al[5], 0.0f);
    }

    // warp-reduce all 65 entries (inactive warps contribute zeros)
#pragma unroll
    for (int k = 0; k < 4; k++) {
        const float v = wredsum(S[k]);
        if (lane == 0) sE[warp][k] = v;
    }
#pragma unroll
    for (int k = 0; k < 10; k++) {
        const float v = wredsum(M2[k]);
        if (lane == 0) sE[warp][4 + k] = v;
    }
#pragma unroll
    for (int a = 0; a < 4; a++)
#pragma unroll
        for (int jj = 0; jj < 6; jj++) {
            const float v = wredsum(S[a] * al[jj]);
            if (lane == 0) sE[warp][14 + a * 6 + jj] = v;
        }
#pragma unroll
    for (int a = 0; a < 6; a++)
#pragma unroll
        for (int b = 0; b < 6; b++) {
            if (b < a) continue;
            const float v = wredsum(nvf * al[a] * al[b]);
            if (lane == 0) sE[warp][38 + (a * 6 - a * (a - 1) / 2 + (b - a))] = v;
        }
#pragma unroll
    for (int jj = 0; jj < 6; jj++) {
        const float v = wredsum(nvf * al[jj]);
        if (lane == 0) sE[warp][59 + jj] = v;
    }
    __syncthreads();

    const int t = threadIdx.x;
    if (t < 65) {
        g_part[t][blockIdx.x] = (sE[0][t] + sE[1][t]) + (sE[2][t] + sE[3][t]);
    }
}

// ---------------------------------------------------------------------------
// k_bn: parallel reduce of g_part (8 threads per entry), then per-channel
// BN-folded param derivation in double precision.
// ---------------------------------------------------------------------------
__global__ void __launch_bounds__(544) k_bn(const float* __restrict__ W,
                                            const float* __restrict__ gamma,
                                            const float* __restrict__ beta) {
    __shared__ float sp8[65][8];
    __shared__ float s_acc[65];
    const int t = threadIdx.x;
    if (t < 520) {
        const int e = t >> 3;
        const int s = t & 7;
        const float* row = g_part[e];
        float acc = 0.0f;
        for (int k = 0; k < 59; k++) {            // 469 <= 8*59
            const int idx = s + 8 * k;
            if (idx < SBLK) acc += row[idx];
        }
        sp8[e][s] = acc;
    }
    __syncthreads();
    if (t < 65) {
        const float* r = sp8[t];
        s_acc[t] = ((r[0] + r[1]) + (r[2] + r[3])) + ((r[4] + r[5]) + (r[6] + r[7]));
    }
    __syncthreads();
    if (t >= 64) return;
    const int o = t;

    const int pidx[10] = {0, 1, 2, 3, 0, 1, 2, 0, 1, 2};
    const int aidx[10] = {-1, -1, -1, -1, 0, 1, 2, 3, 4, 5};

    double w[10];
#pragma unroll
    for (int cc = 0; cc < 10; cc++) w[cc] = (double)W[o * 10 + cc];
    const double NP = (double)NPIL * (double)PPTS;

    double mean = 0.0;
#pragma unroll
    for (int a = 0; a < 10; a++) {
        double g1 = (double)s_acc[pidx[a]];
        if (aidx[a] >= 0) g1 -= (double)s_acc[59 + aidx[a]];
        mean += w[a] * g1;
    }
    mean /= NP;

    double e2 = 0.0;
#pragma unroll
    for (int a = 0; a < 10; a++) {
#pragma unroll
        for (int b = 0; b < 10; b++) {
            if (b < a) continue;
            const int pa = pidx[a], pb = pidx[b];
            const int i4 = (pa <= pb) ? pa : pb;
            const int j4 = (pa <= pb) ? pb : pa;
            double g2 = (double)s_acc[4 + (i4 * 4 - i4 * (i4 - 1) / 2 + (j4 - i4))];
            if (aidx[a] >= 0) g2 -= (double)s_acc[14 + pb * 6 + aidx[a]];
            if (aidx[b] >= 0) g2 -= (double)s_acc[14 + pa * 6 + aidx[b]];
            if (aidx[a] >= 0 && aidx[b] >= 0) {
                const int i6 = (aidx[a] <= aidx[b]) ? aidx[a] : aidx[b];
                const int j6 = (aidx[a] <= aidx[b]) ? aidx[b] : aidx[a];
                g2 += (double)s_acc[38 + (i6 * 6 - i6 * (i6 - 1) / 2 + (j6 - i6))];
            }
            e2 += w[a] * w[b] * g2 * ((a == b) ? 1.0 : 2.0);
        }
    }
    e2 /= NP;

    const double var = e2 - mean * mean;
    const double aa = (double)gamma[o] / sqrt(var + 1e-3);
    const double bb = (double)beta[o] - mean * aa;
    float* p = g_params + o * 16;
    p[0]  = (float)(aa * (w[0] + w[4] + w[7]));
    p[1]  = (float)(aa * (w[1] + w[5] + w[8]));
    p[2]  = (float)(aa * (w[2] + w[6] + w[9]));
    p[3]  = (float)(aa * w[3]);
    p[4]  = (float)(aa * w[4]);
    p[5]  = (float)(aa * w[5]);
    p[6]  = (float)(aa * w[6]);
    p[7]  = (float)(aa * w[7]);
    p[8]  = (float)(aa * w[8]);
    p[9]  = (float)(aa * w[9]);
    p[10] = (float)bb;
    p[11] = 0.0f;
    p[12] = 0.0f; p[13] = 0.0f; p[14] = 0.0f; p[15] = 0.0f;
}

// ---------------------------------------------------------------------------
// k_out: warp = pillar, SINGLE resident wave (592 blocks = 4/SM).
// Only wc0/wc1 live across the hot loop; the pb coefficient vectors are
// reloaded post-loop via __ldg (L1/L2-hot) to keep registers low.
// max_p(pb + d_p) == pb + max_p(d_p).
// ---------------------------------------------------------------------------
__global__ void __launch_bounds__(256) k_out(const float4* __restrict__ pts,
                                             const int* __restrict__ nvs,
                                             float* __restrict__ out) {
    __shared__ float4 sp[8][32];
    const int lane = threadIdx.x & 31;
    const int warp = threadIdx.x >> 5;
    const int gw = blockIdx.x * 8 + warp;
    const int nw = gridDim.x * 8;

    const float4* pp = (const float4*)g_params;
    const float4 wc0 = pp[lane * 4 + 0];
    const float4 wc1 = pp[(lane + 32) * 4 + 0];

    int i = gw;
    if (i >= NPIL) return;
    float4 q = pts[i * PPTS + lane];
    int nv = nvs[i];

    for (;;) {
        sp[warp][lane] = q;
        const float4 pm = g_pm[2 * i];        // consumed after the loop
        const float4 pc = g_pm[2 * i + 1];
        __syncwarp();

        const int inext = i + nw;
        const bool more = inext < NPIL;
        float4 qn; int nvn = 0;
        if (more) {                            // prefetch next pillar
            qn = pts[inext * PPTS + lane];
            nvn = nvs[inext];
        }

        const float4* s4 = sp[warp];
        float a0 = -FLT_MAX, b0 = -FLT_MAX, a1 = -FLT_MAX, b1 = -FLT_MAX;
        int p = 0;
        for (; p + 2 <= nv; p += 2) {
            const float4 r0 = s4[p];
            const float4 r1 = s4[p + 1];
            a0 = fmaxf(a0, fmaf(r0.x, wc0.x, fmaf(r0.y, wc0.y, fmaf(r0.z, wc0.z, r0.w * wc0.w))));
            b0 = fmaxf(b0, fmaf(r1.x, wc0.x, fmaf(r1.y, wc0.y, fmaf(r1.z, wc0.z, r1.w * wc0.w))));
            a1 = fmaxf(a1, fmaf(r0.x, wc1.x, fmaf(r0.y, wc1.y, fmaf(r0.z, wc1.z, r0.w * wc1.w))));
            b1 = fmaxf(b1, fmaf(r1.x, wc1.x, fmaf(r1.y, wc1.y, fmaf(r1.z, wc1.z, r1.w * wc1.w))));
        }
        if (p < nv) {
            const float4 r0 = s4[p];
            a0 = fmaxf(a0, fmaf(r0.x, wc0.x, fmaf(r0.y, wc0.y, fmaf(r0.z, wc0.z, r0.w * wc0.w))));
            a1 = fmaxf(a1, fmaf(r0.x, wc1.x, fmaf(r0.y, wc1.y, fmaf(r0.z, wc1.z, r0.w * wc1.w))));
        }
        __syncwarp();

        // pb coefficient vectors: reloaded here (not live through the loop)
        const float4 m0v = __ldg(&pp[lane * 4 + 1]);
        const float4 t0v = __ldg(&pp[lane * 4 + 2]);
        const float4 m1v = __ldg(&pp[(lane + 32) * 4 + 1]);
        const float4 t1v = __ldg(&pp[(lane + 32) * 4 + 2]);
        const float pb0 = t0v.z - (pm.x * m0v.x + pm.y * m0v.y + pm.z * m0v.z)
                                - (pc.x * m0v.w + pc.y * t0v.x + pc.z * t0v.y);
        const float pb1 = t1v.z - (pm.x * m1v.x + pm.y * m1v.y + pm.z * m1v.z)
                                - (pc.x * m1v.w + pc.y * t1v.x + pc.z * t1v.y);

        float r0 = pb0 + fmaxf(a0, b0);
        float r1 = pb1 + fmaxf(a1, b1);
        if (nv < PPTS) {   // masked points contribute exactly b pre-ReLU
            r0 = fmaxf(r0, t0v.z);
            r1 = fmaxf(r1, t1v.z);
        }
        out[i * 64 + lane]      = fmaxf(r0, 0.0f);
        out[i * 64 + 32 + lane] = fmaxf(r1, 0.0f);

        if (!more) break;
        i = inext; q = qn; nv = nvn;
    }
}

extern "C" void kernel_launch(void* const* d_in, const int* in_sizes, int n_in,
                              void* d_out, int out_size) {
    const float4* feats  = (const float4*)d_in[0];
    const int*    nvs    = (const int*)d_in[1];
    const int4*   coords = (const int4*)d_in[2];
    const float*  W      = (const float*)d_in[3];
    const float*  gamma  = (const float*)d_in[4];
    const float*  beta   = (const float*)d_in[5];
    float* out = (float*)d_out;

    k_stats<<<SBLK, 128>>>(feats, nvs, coords);
    k_bn<<<1, 544>>>(W, gamma, beta);
    k_out<<<592, 256>>>(feats, nvs, out);
}

// round 15
// speedup vs baseline: 1.1620x; 1.1205x over previous
#include <cuda_runtime.h>
#include <math.h>
#include <float.h>

#define NPIL 60000
#define PPTS 32
#define SBLK 938   // k_stats: 128 thr/block, 2 threads/pillar, 64 pillars/block

// moment partials, entry-major for coalesced reduction:
// entry t: [0..3]=M1(sum u), [4..13]=M2 tri4, [14..37]=X[i*6+j]=sum(S_i*alpha_j),
//          [38..58]=A2 tri6 (nv*alpha_a*alpha_b), [59..64]=A1 (nv*alpha_j)
static __device__ float g_part[65][SBLK];
// per-channel folded params, 16 floats each (4 float4s)
static __device__ float g_params[64 * 16];
// per-pillar mean + center: [2i]={mx,my,mz,-}, [2i+1]={cx,cy,cz,-}
static __device__ float4 g_pm[NPIL * 2];

__device__ __forceinline__ float wredsum(float v) {
#pragma unroll
    for (int s = 16; s > 0; s >>= 1) v += __shfl_xor_sync(0xffffffffu, v, s);
    return v;
}

// ---------------------------------------------------------------------------
// k_stats: 2 threads per pillar + coalesced smem staging.
// Warp owns 16 consecutive pillars (60000 % 16 == 0 -> warp-uniform validity).
// Stage: 16 warp-LDGs read the full 16x32 float4 tile (perfectly coalesced).
// Process: lane (pillar=lane>>1, half=lane&1) streams its 16 points from smem
// in ROTATED order (k+lane)&15 -> conflict-free LDS.
// Pair-merge S / unmasked-xyz via shfl_xor(1); even lane owns alpha products.
// Epilogue: all 65 moment entries computed on the fly, warp-reduced once.
// ---------------------------------------------------------------------------
__global__ void __launch_bounds__(128) k_stats(const float4* __restrict__ pts,
                                               const int* __restrict__ nvs,
                                               const int4* __restrict__ coords) {
    __shared__ float4 tile[4][16][32];   // [warp][pillar][point] : 32KB
    __shared__ float sE[4][65];
    const int lane = threadIdx.x & 31;
    const int warp = threadIdx.x >> 5;
    const int warp_base = blockIdx.x * 64 + warp * 16;
    const bool wok = (warp_base < NPIL);       // warp-uniform
    const int ppil = lane >> 1;                // pillar within warp
    const int half = lane & 1;
    const int i = warp_base + ppil;

    float S[4]  = {0.0f, 0.0f, 0.0f, 0.0f};
    float M2[10];
#pragma unroll
    for (int k = 0; k < 10; k++) M2[k] = 0.0f;
    float al[6] = {0.0f, 0.0f, 0.0f, 0.0f, 0.0f, 0.0f};
    float nvf = 0.0f;

    if (wok) {
        // stage 16 pillars x 32 points, fully coalesced (512B per LDG)
        const float4* __restrict__ gp = pts + warp_base * PPTS;
#pragma unroll
        for (int t = 0; t < 16; t++) {
            const int flat = t * 32 + lane;
            tile[warp][flat >> 5][flat & 31] = gp[flat];
        }
        __syncwarp();

        const int nv = nvs[i];
        float tx = 0.0f, ty = 0.0f, tz = 0.0f;   // unmasked xyz partial (this half)

#pragma unroll
        for (int k = 0; k < 16; k++) {
            const int pt = half * 16 + ((k + lane) & 15);  // rotated: no conflicts
            const float4 q = tile[warp][ppil][pt];
            const float m = (pt < nv) ? 1.0f : 0.0f;
            tx += q.x; ty += q.y; tz += q.z;
            const float ux = q.x * m, uy = q.y * m, uz = q.z * m, uw = q.w * m;
            S[0] += ux; S[1] += uy; S[2] += uz; S[3] += uw;
            M2[0] = fmaf(ux, ux, M2[0]); M2[1] = fmaf(ux, uy, M2[1]);
            M2[2] = fmaf(ux, uz, M2[2]); M2[3] = fmaf(ux, uw, M2[3]);
            M2[4] = fmaf(uy, uy, M2[4]); M2[5] = fmaf(uy, uz, M2[5]);
            M2[6] = fmaf(uy, uw, M2[6]); M2[7] = fmaf(uz, uz, M2[7]);
            M2[8] = fmaf(uz, uw, M2[8]); M2[9] = fmaf(uw, uw, M2[9]);
        }

        // merge partner halves (adjacent lanes share a pillar)
        const float Sx = S[0] + __shfl_xor_sync(0xffffffffu, S[0], 1);
        const float Sy = S[1] + __shfl_xor_sync(0xffffffffu, S[1], 1);
        const float Sz = S[2] + __shfl_xor_sync(0xffffffffu, S[2], 1);
        const float Sw = S[3] + __shfl_xor_sync(0xffffffffu, S[3], 1);
        const float Tx = tx + __shfl_xor_sync(0xffffffffu, tx, 1);
        const float Ty = ty + __shfl_xor_sync(0xffffffffu, ty, 1);
        const float Tz = tz + __shfl_xor_sync(0xffffffffu, tz, 1);

        if (half == 0) {
            S[0] = Sx; S[1] = Sy; S[2] = Sz; S[3] = Sw;
            const int4 c = coords[i];
            nvf = (float)nv;
            const float inv = 1.0f / nvf;
            al[0] = Tx * inv;                  // mean over ALL 32 points, / nv (ref)
            al[1] = Ty * inv;
            al[2] = Tz * inv;
            al[3] = (float)c.w * 0.2f + 0.1f;
            al[4] = (float)c.z * 0.2f - 39.9f;
            al[5] = (float)c.y * 4.0f - 1.0f;
            g_pm[2 * i]     = make_float4(al[0], al[1], al[2], 0.0f);
            g_pm[2 * i + 1] = make_float4(al[3], al[4], al[5], 0.0f);
        } else {
            S[0] = 0.0f; S[1] = 0.0f; S[2] = 0.0f; S[3] = 0.0f;  // no double count
        }
    }

    // warp-reduce all 65 entries (odd lanes / inactive warps contribute zeros
    // except M2, which is a true additive per-thread partial)
#pragma unroll
    for (int k = 0; k < 4; k++) {
        const float v = wredsum(S[k]);
        if (lane == 0) sE[warp][k] = v;
    }
#pragma unroll
    for (int k = 0; k < 10; k++) {
        const float v = wredsum(M2[k]);
        if (lane == 0) sE[warp][4 + k] = v;
    }
#pragma unroll
    for (int a = 0; a < 4; a++)
#pragma unroll
        for (int jj = 0; jj < 6; jj++) {
            const float v = wredsum(S[a] * al[jj]);
            if (lane == 0) sE[warp][14 + a * 6 + jj] = v;
        }
#pragma unroll
    for (int a = 0; a < 6; a++)
#pragma unroll
        for (int b = 0; b < 6; b++) {
            if (b < a) continue;
            const float v = wredsum(nvf * al[a] * al[b]);
            if (lane == 0) sE[warp][38 + (a * 6 - a * (a - 1) / 2 + (b - a))] = v;
        }
#pragma unroll
    for (int jj = 0; jj < 6; jj++) {
        const float v = wredsum(nvf * al[jj]);
        if (lane == 0) sE[warp][59 + jj] = v;
    }
    __syncthreads();

    const int t = threadIdx.x;
    if (t < 65) {
        g_part[t][blockIdx.x] = (sE[0][t] + sE[1][t]) + (sE[2][t] + sE[3][t]);
    }
}

// ---------------------------------------------------------------------------
// k_bn: parallel reduce of g_part (8 threads per entry), then per-channel
// BN-folded param derivation in double precision.
// ---------------------------------------------------------------------------
__global__ void __launch_bounds__(544) k_bn(const float* __restrict__ W,
                                            const float* __restrict__ gamma,
                                            const float* __restrict__ beta) {
    __shared__ float sp8[65][8];
    __shared__ float s_acc[65];
    const int t = threadIdx.x;
    if (t < 520) {
        const int e = t >> 3;
        const int s = t & 7;
        const float* row = g_part[e];
        float acc = 0.0f;
        for (int k = 0; k < 118; k++) {           // 938 <= 8*118
            const int idx = s + 8 * k;
            if (idx < SBLK) acc += row[idx];
        }
        sp8[e][s] = acc;
    }
    __syncthreads();
    if (t < 65) {
        const float* r = sp8[t];
        s_acc[t] = ((r[0] + r[1]) + (r[2] + r[3])) + ((r[4] + r[5]) + (r[6] + r[7]));
    }
    __syncthreads();
    if (t >= 64) return;
    const int o = t;

    const int pidx[10] = {0, 1, 2, 3, 0, 1, 2, 0, 1, 2};
    const int aidx[10] = {-1, -1, -1, -1, 0, 1, 2, 3, 4, 5};

    double w[10];
#pragma unroll
    for (int cc = 0; cc < 10; cc++) w[cc] = (double)W[o * 10 + cc];
    const double NP = (double)NPIL * (double)PPTS;

    double mean = 0.0;
#pragma unroll
    for (int a = 0; a < 10; a++) {
        double g1 = (double)s_acc[pidx[a]];
        if (aidx[a] >= 0) g1 -= (double)s_acc[59 + aidx[a]];
        mean += w[a] * g1;
    }
    mean /= NP;

    double e2 = 0.0;
#pragma unroll
    for (int a = 0; a < 10; a++) {
#pragma unroll
        for (int b = 0; b < 10; b++) {
            if (b < a) continue;
            const int pa = pidx[a], pb = pidx[b];
            const int i4 = (pa <= pb) ? pa : pb;
            const int j4 = (pa <= pb) ? pb : pa;
            double g2 = (double)s_acc[4 + (i4 * 4 - i4 * (i4 - 1) / 2 + (j4 - i4))];
            if (aidx[a] >= 0) g2 -= (double)s_acc[14 + pb * 6 + aidx[a]];
            if (aidx[b] >= 0) g2 -= (double)s_acc[14 + pa * 6 + aidx[b]];
            if (aidx[a] >= 0 && aidx[b] >= 0) {
                const int i6 = (aidx[a] <= aidx[b]) ? aidx[a] : aidx[b];
                const int j6 = (aidx[a] <= aidx[b]) ? aidx[b] : aidx[a];
                g2 += (double)s_acc[38 + (i6 * 6 - i6 * (i6 - 1) / 2 + (j6 - i6))];
            }
            e2 += w[a] * w[b] * g2 * ((a == b) ? 1.0 : 2.0);
        }
    }
    e2 /= NP;

    const double var = e2 - mean * mean;
    const double aa = (double)gamma[o] / sqrt(var + 1e-3);
    const double bb = (double)beta[o] - mean * aa;
    float* p = g_params + o * 16;
    p[0]  = (float)(aa * (w[0] + w[4] + w[7]));
    p[1]  = (float)(aa * (w[1] + w[5] + w[8]));
    p[2]  = (float)(aa * (w[2] + w[6] + w[9]));
    p[3]  = (float)(aa * w[3]);
    p[4]  = (float)(aa * w[4]);
    p[5]  = (float)(aa * w[5]);
    p[6]  = (float)(aa * w[6]);
    p[7]  = (float)(aa * w[7]);
    p[8]  = (float)(aa * w[8]);
    p[9]  = (float)(aa * w[9]);
    p[10] = (float)bb;
    p[11] = 0.0f;
    p[12] = 0.0f; p[13] = 0.0f; p[14] = 0.0f; p[15] = 0.0f;
}

// ---------------------------------------------------------------------------
// k_out: warp = pillar (R6 proven config: grid 1184, params in registers,
// prefetch, post-loop pb) + DUPLICATE-FILL: masked tile slots get point 0
// (a valid duplicate, max unchanged; nv >= 1 per reference randint(1,P+1))
// so the inner loop is fixed-step-4 with no remainder.
// max_p(pb + d_p) == pb + max_p(d_p).
// ---------------------------------------------------------------------------
__global__ void __launch_bounds__(256) k_out(const float4* __restrict__ pts,
                                             const int* __restrict__ nvs,
                                             float* __restrict__ out) {
    __shared__ float4 sp[8][32];
    const int lane = threadIdx.x & 31;
    const int warp = threadIdx.x >> 5;
    const int gw = blockIdx.x * 8 + warp;
    const int nw = gridDim.x * 8;

    const float4* pp = (const float4*)g_params;
    const float4 wc0 = pp[lane * 4 + 0];
    const float4 m0v = pp[lane * 4 + 1];          // {aW4,aW5,aW6,aW7}
    const float4 t0v = pp[lane * 4 + 2];          // {aW8,aW9,b,pad}
    const float4 wc1 = pp[(lane + 32) * 4 + 0];
    const float4 m1v = pp[(lane + 32) * 4 + 1];
    const float4 t1v = pp[(lane + 32) * 4 + 2];

    int i = gw;
    if (i >= NPIL) return;
    float4 q = pts[i * PPTS + lane];
    int nv = nvs[i];

    for (;;) {
        sp[warp][lane] = q;
        const float4 pm = g_pm[2 * i];        // consumed after the loop
        const float4 pc = g_pm[2 * i + 1];
        __syncwarp();
        if (lane >= nv) sp[warp][lane] = sp[warp][0];   // duplicate-fill
        __syncwarp();

        const int inext = i + nw;
        const bool more = inext < NPIL;
        float4 qn; int nvn = 0;
        if (more) {                            // prefetch next pillar
            qn = pts[inext * PPTS + lane];
            nvn = nvs[inext];
        }

        const float4* s4 = sp[warp];
        float a0 = -FLT_MAX, b0 = -FLT_MAX, a1 = -FLT_MAX, b1 = -FLT_MAX;
        for (int p = 0; p < nv; p += 4) {      // p<=28 -> p+3<=31 always in-tile
            float4 r0 = s4[p];
            float4 r1 = s4[p + 1];
            a0 = fmaxf(a0, fmaf(r0.x, wc0.x, fmaf(r0.y, wc0.y, fmaf(r0.z, wc0.z, r0.w * wc0.w))));
            b0 = fmaxf(b0, fmaf(r1.x, wc0.x, fmaf(r1.y, wc0.y, fmaf(r1.z, wc0.z, r1.w * wc0.w))));
            a1 = fmaxf(a1, fmaf(r0.x, wc1.x, fmaf(r0.y, wc1.y, fmaf(r0.z, wc1.z, r0.w * wc1.w))));
            b1 = fmaxf(b1, fmaf(r1.x, wc1.x, fmaf(r1.y, wc1.y, fmaf(r1.z, wc1.z, r1.w * wc1.w))));
            r0 = s4[p + 2];
            r1 = s4[p + 3];
            a0 = fmaxf(a0, fmaf(r0.x, wc0.x, fmaf(r0.y, wc0.y, fmaf(r0.z, wc0.z, r0.w * wc0.w))));
            b0 = fmaxf(b0, fmaf(r1.x, wc0.x, fmaf(r1.y, wc0.y, fmaf(r1.z, wc0.z, r1.w * wc0.w))));
            a1 = fmaxf(a1, fmaf(r0.x, wc1.x, fmaf(r0.y, wc1.y, fmaf(r0.z, wc1.z, r0.w * wc1.w))));
            b1 = fmaxf(b1, fmaf(r1.x, wc1.x, fmaf(r1.y, wc1.y, fmaf(r1.z, wc1.z, r1.w * wc1.w))));
        }
        __syncwarp();

        const float pb0 = t0v.z - (pm.x * m0v.x + pm.y * m0v.y + pm.z * m0v.z)
                                - (pc.x * m0v.w + pc.y * t0v.x + pc.z * t0v.y);
        const float pb1 = t1v.z - (pm.x * m1v.x + pm.y * m1v.y + pm.z * m1v.z)
                                - (pc.x * m1v.w + pc.y * t1v.x + pc.z * t1v.y);

        float r0 = pb0 + fmaxf(a0, b0);
        float r1 = pb1 + fmaxf(a1, b1);
        if (nv < PPTS) {   // masked points contribute exactly b pre-ReLU
            r0 = fmaxf(r0, t0v.z);
            r1 = fmaxf(r1, t1v.z);
        }
        out[i * 64 + lane]      = fmaxf(r0, 0.0f);
        out[i * 64 + 32 + lane] = fmaxf(r1, 0.0f);

        if (!more) break;
        i = inext; q = qn; nv = nvn;
    }
}

extern "C" void kernel_launch(void* const* d_in, const int* in_sizes, int n_in,
                              void* d_out, int out_size) {
    const float4* feats  = (const float4*)d_in[0];
    const int*    nvs    = (const int*)d_in[1];
    const int4*   coords = (const int4*)d_in[2];
    const float*  W      = (const float*)d_in[3];
    const float*  gamma  = (const float*)d_in[4];
    const float*  beta   = (const float*)d_in[5];
    float* out = (float*)d_out;

    k_stats<<<SBLK, 128>>>(feats, nvs, coords);
    k_bn<<<1, 544>>>(W, gamma, beta);
    k_out<<<1184, 256>>>(feats, nvs, out);
}